// round 10
// baseline (speedup 1.0000x reference)
#include <cuda_runtime.h>
#include <cuda_fp16.h>
#include <stdint.h>

// QLoRALinear: out[128,11008] = x @ dequant_int4(W) + 2*(x@A^T)@B^T
// Round 10: heterogeneous grid — tensor-core blocks (fp16 mma, groups 0..27)
// and FFMA2 CUDA-core blocks (f32x2, groups 28..31) run CONCURRENTLY in one
// launch, using both the tensor pipe and the fma pipe of each SM.

#define OUTD 11008
#define IND  4096
#define MTOT 128
#define RLORA 16

// ---- tensor side ----
#define NTILE 64
#define KSPLIT_T 4
#define KC 64
#define NCH 14                       // chunks per tensor slab (896k = 7 groups)
#define NGRP 7
#define NCHUNK_TOT (IND / KC)
#define ROWH 72

#define XH_OFF 0
#define WQ_OFF 9216
#define BUF_H  13824
#define SMEM_BYTES (2 * BUF_H * 2)   // 55296

// ---- fma side (R2-style) ----
#define F_KBASE 3584                 // groups 28..31
#define F_KSLICE 512
#define F_KC 32
#define F_NCHUNK 16
#define F_OTILE 128
#define F_GPS 4                      // groups per fma slice
#define F_XS_STRIDE 132
#define F_WS_BLK 260
#define NFMA 86                      // fma blocks (one slab)

#define KSLABS 5                     // 4 tensor + 1 fma

// ---- device scratch ----
__device__ __align__(16) uint16_t g_xh[NCHUNK_TOT * MTOT * ROWH];
__device__ __align__(16) float    g_xa4[4 * MTOT * RLORA];
__device__ float g_partial[KSLABS * MTOT * OUTD];   // 28.2 MB

// ---------------------------------------------------------------------------
__device__ __forceinline__ uint32_t pack_f16x2(float lo, float hi) {
    uint32_t r;
    asm("cvt.rn.f16x2.f32 %0, %1, %2;" : "=r"(r) : "f"(hi), "f"(lo));
    return r;
}
__device__ __forceinline__ uint32_t smem_u32(const void* p) {
    uint32_t a;
    asm("{ .reg .u64 t; cvta.to.shared.u64 t, %1; cvt.u32.u64 %0, t; }"
        : "=r"(a) : "l"(p));
    return a;
}
__device__ __forceinline__ void cp16(uint32_t dst, const void* src) {
    asm volatile("cp.async.cg.shared.global [%0], [%1], 16;"
                 :: "r"(dst), "l"(src) : "memory");
}
__device__ __forceinline__ void mma16816(float* d, const uint32_t* a,
                                         uint32_t b0, uint32_t b1) {
    asm volatile(
        "mma.sync.aligned.m16n8k16.row.col.f32.f16.f16.f32 "
        "{%0,%1,%2,%3}, {%4,%5,%6,%7}, {%8,%9}, {%0,%1,%2,%3};"
        : "+f"(d[0]), "+f"(d[1]), "+f"(d[2]), "+f"(d[3])
        : "r"(a[0]), "r"(a[1]), "r"(a[2]), "r"(a[3]), "r"(b0), "r"(b1));
}
__device__ __forceinline__ void ldm4(uint32_t* r, uint32_t addr) {
    asm volatile("ldmatrix.sync.aligned.m8n8.x4.shared.b16 {%0,%1,%2,%3}, [%4];"
                 : "=r"(r[0]), "=r"(r[1]), "=r"(r[2]), "=r"(r[3]) : "r"(addr));
}
__device__ __forceinline__ unsigned long long pack2(float v) {
    unsigned long long r;
    asm("mov.b64 %0, {%1, %1};" : "=l"(r) : "f"(v));
    return r;
}
__device__ __forceinline__ void ffma2(unsigned long long &d,
                                      unsigned long long a,
                                      unsigned long long b) {
    asm("fma.rn.f32x2 %0, %1, %2, %0;" : "+l"(d) : "l"(a), "l"(b));
}

// ---------------------------------------------------------------------------
// Prep: x -> fp16 tile image + xa slab. grid (128, 4), 256 thr.
// ---------------------------------------------------------------------------
__global__ __launch_bounds__(256) void prep_kernel(const float* __restrict__ x,
                                                   const float* __restrict__ A) {
    const int m  = blockIdx.x;
    const int kq = blockIdx.y;
    const int t  = threadIdx.x;
    const int wid = t >> 5, lane = t & 31;
    const int k0 = kq * 1024 + t * 4;

    const float4 xv = *(const float4*)(x + (size_t)m * IND + k0);

    const int chunk = k0 >> 6;
    const int koff  = k0 & 63;
    uint2 hp;
    hp.x = pack_f16x2(xv.x, xv.y);
    hp.y = pack_f16x2(xv.z, xv.w);
    *(uint2*)(g_xh + ((size_t)chunk * MTOT + m) * ROWH + koff) = hp;

    float acc[RLORA];
#pragma unroll
    for (int r = 0; r < RLORA; r++) {
        const float4 a4 = *(const float4*)(A + (size_t)r * IND + k0);
        float s = xv.x * a4.x;
        s = fmaf(xv.y, a4.y, s);
        s = fmaf(xv.z, a4.z, s);
        s = fmaf(xv.w, a4.w, s);
        acc[r] = s;
    }
#pragma unroll
    for (int r = 0; r < RLORA; r++)
#pragma unroll
        for (int off = 16; off > 0; off >>= 1)
            acc[r] += __shfl_xor_sync(0xffffffffu, acc[r], off);

    __shared__ float red[8][RLORA];
    if (lane == 0)
#pragma unroll
        for (int r = 0; r < RLORA; r++) red[wid][r] = acc[r];
    __syncthreads();
    if (t < RLORA) {
        float s = 0.0f;
#pragma unroll
        for (int w = 0; w < 8; w++) s += red[w][t];
        g_xa4[(kq * MTOT + m) * RLORA + t] = s;
    }
}

// ---------------------------------------------------------------------------
// Combined main kernel. grid = 86 fma blocks + 688 tensor blocks (1D).
// ---------------------------------------------------------------------------
__global__ __launch_bounds__(256, 2) void qmain_kernel(
    const float* __restrict__ x,
    const int*   __restrict__ W,
    const int*   __restrict__ zeros,
    const float* __restrict__ scales,
    const float* __restrict__ loraB)
{
    extern __shared__ __align__(16) uint16_t smdyn[];
    __shared__ float sS[NGRP][NTILE];
    __shared__ int   zS[NGRP][NTILE];
    __shared__ __align__(16) float sB[NTILE][RLORA];
    __shared__ __align__(16) float sxa[MTOT][RLORA];

    const int t = threadIdx.x;
    const int bx = blockIdx.x;

    if (bx < NFMA) {
        // ================= FFMA2 path (R2 inner loop), groups 28..31 =========
        float* xs = (float*)smdyn;                       // [32][132]
        float* ws = xs + F_KC * F_XS_STRIDE;             // 16 * 260
        float2* szs = (float2*)(ws + 16 * F_WS_BLK);     // [4][128]

        const int to = t & 15;
        const int tm = t >> 4;
        const int obase = bx * F_OTILE;

        // (scale, zero*scale) for groups 28..31
        for (int idx = t; idx < F_GPS * F_OTILE; idx += 256) {
            const int g = idx >> 7;
            const int o = idx & 127;
            const float s = scales[(size_t)(28 + g) * OUTD + obase + o];
            const float z = (float)zeros[(size_t)(28 + g) * OUTD + obase + o];
            szs[g * F_OTILE + o] = make_float2(s, z * s);
        }

        unsigned long long acc[4][8];
#pragma unroll
        for (int p = 0; p < 4; p++)
#pragma unroll
            for (int o = 0; o < 8; o++) acc[p][o] = 0ull;

        const int w_kl = t >> 3;
        const int w_oi = t & 7;
        const int x_m  = t >> 1;
        const int x_kh = t & 1;
        const int ws_off = to * F_WS_BLK;
        const int m0 = 8 * tm;

        __syncthreads();

#pragma unroll 1
        for (int c = 0; c < F_NCHUNK; c++) {
            const int k0 = F_KBASE + c * F_KC;
            const int kg = c >> 2;

            {
                const int* Wp = W + (size_t)(k0 + w_kl) * OUTD + obase + w_oi * 16;
#pragma unroll
                for (int q = 0; q < 4; q++) {
                    const int4 v = *(const int4*)(Wp + 4 * q);
                    const int ol = w_oi * 16 + 4 * q;
                    const float4 sz0 = *(const float4*)&szs[kg * F_OTILE + ol];
                    const float4 sz1 = *(const float4*)&szs[kg * F_OTILE + ol + 2];
                    float4 wv;
                    wv.x = fmaf((float)v.x, sz0.x, -sz0.y);
                    wv.y = fmaf((float)v.y, sz0.z, -sz0.w);
                    wv.z = fmaf((float)v.z, sz1.x, -sz1.y);
                    wv.w = fmaf((float)v.w, sz1.z, -sz1.w);
                    *(float4*)&ws[(2 * w_oi + (q >> 1)) * F_WS_BLK + w_kl * 8 + (q & 1) * 4] = wv;
                }
            }
            {
                const float* xp = x + (size_t)x_m * IND + k0 + x_kh * 16;
#pragma unroll
                for (int q = 0; q < 4; q++) {
                    const float4 v = *(const float4*)(xp + 4 * q);
                    const int kk = x_kh * 16 + 4 * q;
                    xs[(kk + 0) * F_XS_STRIDE + x_m] = v.x;
                    xs[(kk + 1) * F_XS_STRIDE + x_m] = v.y;
                    xs[(kk + 2) * F_XS_STRIDE + x_m] = v.z;
                    xs[(kk + 3) * F_XS_STRIDE + x_m] = v.w;
                }
            }
            __syncthreads();

#pragma unroll 8
            for (int kk = 0; kk < F_KC; kk++) {
                const ulonglong2 xp01 = *(const ulonglong2*)&xs[kk * F_XS_STRIDE + m0];
                const ulonglong2 xp23 = *(const ulonglong2*)&xs[kk * F_XS_STRIDE + m0 + 4];
                const float4 w0 = *(const float4*)&ws[ws_off + kk * 8];
                const float4 w1 = *(const float4*)&ws[ws_off + kk * 8 + 4];

                unsigned long long wd[8];
                wd[0] = pack2(w0.x); wd[1] = pack2(w0.y);
                wd[2] = pack2(w0.z); wd[3] = pack2(w0.w);
                wd[4] = pack2(w1.x); wd[5] = pack2(w1.y);
                wd[6] = pack2(w1.z); wd[7] = pack2(w1.w);

#pragma unroll
                for (int o = 0; o < 8; o++) {
                    ffma2(acc[0][o], xp01.x, wd[o]);
                    ffma2(acc[1][o], xp01.y, wd[o]);
                    ffma2(acc[2][o], xp23.x, wd[o]);
                    ffma2(acc[3][o], xp23.y, wd[o]);
                }
            }
            __syncthreads();
        }

        // store to slab 4
        float* pp = g_partial + (size_t)4 * MTOT * OUTD;
        const int og = obase + 8 * to;
#pragma unroll
        for (int p = 0; p < 4; p++) {
            union { unsigned long long u; float2 f; } cv[8];
#pragma unroll
            for (int o = 0; o < 8; o++) cv[o].u = acc[p][o];
            const int r0 = m0 + 2 * p;
            float4 a = make_float4(cv[0].f.x, cv[1].f.x, cv[2].f.x, cv[3].f.x);
            float4 b = make_float4(cv[4].f.x, cv[5].f.x, cv[6].f.x, cv[7].f.x);
            *(float4*)&pp[(size_t)r0 * OUTD + og]     = a;
            *(float4*)&pp[(size_t)r0 * OUTD + og + 4] = b;
            a = make_float4(cv[0].f.y, cv[1].f.y, cv[2].f.y, cv[3].f.y);
            b = make_float4(cv[4].f.y, cv[5].f.y, cv[6].f.y, cv[7].f.y);
            *(float4*)&pp[(size_t)(r0 + 1) * OUTD + og]     = a;
            *(float4*)&pp[(size_t)(r0 + 1) * OUTD + og + 4] = b;
        }
        return;
    }

    // ================= tensor path, groups 0..27 =============================
    const int tb = bx - NFMA;
    const int kq4 = tb & 3;
    const int obase = (tb >> 2) * NTILE;
    const int gbase = kq4 * NGRP;

    const uint32_t smb = smem_u32(smdyn);
    const int lane = t & 31;
    const int wid = t >> 5;
    const int wm = wid & 3;
    const int wo = wid >> 2;

    const int so  = t & 63;
    const int skq = t >> 6;
    const int xrow = t >> 1;
    const int xhalf = t & 1;

    for (int idx = t; idx < NGRP * NTILE; idx += 256) {
        const int g = idx >> 6, o = idx & 63;
        sS[g][o] = scales[(size_t)(gbase + g) * OUTD + obase + o];
        zS[g][o] = zeros[(size_t)(gbase + g) * OUTD + obase + o];
    }

    const int rowA = (lane & 7) + ((lane >> 3) & 1) * 8;
    const int kA   = ((lane >> 4) & 1) * 8;
    const int rowB = (lane & 7) + ((lane >> 4) & 1) * 8;
    const int kB   = ((lane >> 3) & 1) * 8;

    float facc[2][4][4];
    float gacc[2][4][4];
#pragma unroll
    for (int mt = 0; mt < 2; mt++)
#pragma unroll
        for (int ot = 0; ot < 4; ot++)
#pragma unroll
            for (int i = 0; i < 4; i++) { facc[mt][ot][i] = 0.f; gacc[mt][ot][i] = 0.f; }

    auto cpX = [&](int b, int c) {
        const int ck = kq4 * NCH + c;
        const size_t src = ((size_t)ck * MTOT + xrow) * ROWH + xhalf * 32;
        const uint32_t dxh = smb + (b * BUF_H + XH_OFF + xrow * ROWH + xhalf * 32) * 2;
#pragma unroll
        for (int j = 0; j < 4; j++)
            cp16(dxh + j * 16, g_xh + src + j * 8);
        asm volatile("cp.async.commit_group;" ::: "memory");
    };
    auto ldgW = [&](int c, int* qv) {
        const int ck = kq4 * NCH + c;
        const int* Wp = W + (size_t)(ck * KC + skq * 16) * OUTD + obase + so;
#pragma unroll
        for (int p = 0; p < 16; p++) qv[p] = Wp[(size_t)p * OUTD];
    };
    auto stsW = [&](int b, int c, const int* qv) {
        const int z = zS[c >> 1][so];
        uint32_t hp[8];
#pragma unroll
        for (int p = 0; p < 8; p++)
            hp[p] = pack_f16x2((float)(qv[2 * p] - z), (float)(qv[2 * p + 1] - z));
        uint16_t* wq = smdyn + b * BUF_H + WQ_OFF + so * ROWH + skq * 16;
        ((uint4*)wq)[0] = make_uint4(hp[0], hp[1], hp[2], hp[3]);
        ((uint4*)wq)[1] = make_uint4(hp[4], hp[5], hp[6], hp[7]);
    };

    if (kq4 == 0) {
        ((float4*)sB)[t] = ((const float4*)(loraB + (size_t)obase * RLORA))[t];
#pragma unroll
        for (int pass = 0; pass < 2; pass++) {
            const int idx = t + pass * 256;
            float4 s0 = ((const float4*)g_xa4)[idx];
            const float4 s1 = ((const float4*)g_xa4)[idx + 512];
            const float4 s2 = ((const float4*)g_xa4)[idx + 1024];
            const float4 s3 = ((const float4*)g_xa4)[idx + 1536];
            s0.x = 2.0f * (s0.x + s1.x + s2.x + s3.x);
            s0.y = 2.0f * (s0.y + s1.y + s2.y + s3.y);
            s0.z = 2.0f * (s0.z + s1.z + s2.z + s3.z);
            s0.w = 2.0f * (s0.w + s1.w + s2.w + s3.w);
            ((float4*)sxa)[idx] = s0;
        }
    }

    __syncthreads();

    int qv[16];
    ldgW(0, qv);
    cpX(0, 0);
    stsW(0, 0, qv);
    asm volatile("cp.async.wait_group 0;" ::: "memory");
    __syncthreads();

    const int arow = lane >> 2;
    const int acol = (lane & 3) * 2;

    const int aoff0 = XH_OFF + (wm * 32 + 0 * 16 + rowA) * ROWH + kA;
    const int aoff1 = XH_OFF + (wm * 32 + 1 * 16 + rowA) * ROWH + kA;
    const int boff0 = WQ_OFF + (wo * 32 + 0 * 16 + rowB) * ROWH + kB;
    const int boff1 = WQ_OFF + (wo * 32 + 1 * 16 + rowB) * ROWH + kB;

    int buf = 0;
#pragma unroll 1
    for (int c = 0; c < NCH; c++) {
        int qn[16];
        if (c + 1 < NCH) {
            ldgW(c + 1, qn);
            cpX(buf ^ 1, c + 1);
        }

        const uint32_t bb = smb + (buf * BUF_H) * 2;
#pragma unroll
        for (int ks = 0; ks < KC; ks += 16) {
            uint32_t a0[4], a1[4], bq0[4], bq1[4];
            ldm4(a0, bb + (aoff0 + ks) * 2);
            ldm4(a1, bb + (aoff1 + ks) * 2);
            ldm4(bq0, bb + (boff0 + ks) * 2);
            ldm4(bq1, bb + (boff1 + ks) * 2);
#pragma unroll
            for (int ot = 0; ot < 4; ot++) {
                const uint32_t b0 = (ot < 2) ? bq0[2 * ot]     : bq1[2 * (ot - 2)];
                const uint32_t b1 = (ot < 2) ? bq0[2 * ot + 1] : bq1[2 * (ot - 2) + 1];
                mma16816(gacc[0][ot], a0, b0, b1);
                mma16816(gacc[1][ot], a1, b0, b1);
            }
        }

        if (c + 1 < NCH) stsW(buf ^ 1, c + 1, qn);

        if (c & 1) {
            const int g = c >> 1;
#pragma unroll
            for (int ot = 0; ot < 4; ot++) {
                const float2 sv = *(const float2*)&sS[g][wo * 32 + ot * 8 + acol];
#pragma unroll
                for (int mt = 0; mt < 2; mt++) {
                    facc[mt][ot][0] = fmaf(sv.x, gacc[mt][ot][0], facc[mt][ot][0]);
                    facc[mt][ot][1] = fmaf(sv.y, gacc[mt][ot][1], facc[mt][ot][1]);
                    facc[mt][ot][2] = fmaf(sv.x, gacc[mt][ot][2], facc[mt][ot][2]);
                    facc[mt][ot][3] = fmaf(sv.y, gacc[mt][ot][3], facc[mt][ot][3]);
                    gacc[mt][ot][0] = 0.f; gacc[mt][ot][1] = 0.f;
                    gacc[mt][ot][2] = 0.f; gacc[mt][ot][3] = 0.f;
                }
            }
        }

        asm volatile("cp.async.wait_group 0;" ::: "memory");
        __syncthreads();
        buf ^= 1;
    }

    if (kq4 == 0) {
#pragma unroll
        for (int mt = 0; mt < 2; mt++)
#pragma unroll
            for (int half = 0; half < 2; half++) {
                const int r = wm * 32 + mt * 16 + half * 8 + arow;
                const float* xr = sxa[r];
#pragma unroll
                for (int ot = 0; ot < 4; ot++) {
                    const int co = wo * 32 + ot * 8 + acol;
                    const float* B0 = sB[co];
                    const float* B1 = sB[co + 1];
                    float l0 = 0.f, l1 = 0.f;
#pragma unroll
                    for (int rr = 0; rr < RLORA; rr++) {
                        l0 = fmaf(xr[rr], B0[rr], l0);
                        l1 = fmaf(xr[rr], B1[rr], l1);
                    }
                    facc[mt][ot][2 * half + 0] += l0;
                    facc[mt][ot][2 * half + 1] += l1;
                }
            }
    }

    float* pp = g_partial + (size_t)kq4 * MTOT * OUTD;
#pragma unroll
    for (int mt = 0; mt < 2; mt++) {
        const int r0 = wm * 32 + mt * 16 + arow;
#pragma unroll
        for (int ot = 0; ot < 4; ot++) {
            const int cabs = obase + wo * 32 + ot * 8 + acol;
            *(float2*)&pp[(size_t)r0 * OUTD + cabs] =
                make_float2(facc[mt][ot][0], facc[mt][ot][1]);
            *(float2*)&pp[(size_t)(r0 + 8) * OUTD + cabs] =
                make_float2(facc[mt][ot][2], facc[mt][ot][3]);
        }
    }
}

// ---------------------------------------------------------------------------
// Reduce: 5-way partial sum.
// ---------------------------------------------------------------------------
__global__ __launch_bounds__(256) void reduce_kernel(float* __restrict__ out)
{
    const int m = blockIdx.y;
    const int oc = blockIdx.x * 256 + threadIdx.x;
    if (oc >= OUTD / 4) return;
    const int o = 4 * oc;

    float4 s = make_float4(0.f, 0.f, 0.f, 0.f);
#pragma unroll
    for (int p = 0; p < KSLABS; p++) {
        const float4 v = *(const float4*)&g_partial[(size_t)p * MTOT * OUTD +
                                                    (size_t)m * OUTD + o];
        s.x += v.x; s.y += v.y; s.z += v.z; s.w += v.w;
    }
    *(float4*)&out[(size_t)m * OUTD + o] = s;
}

// ---------------------------------------------------------------------------
extern "C" void kernel_launch(void* const* d_in, const int* in_sizes, int n_in,
                              void* d_out, int out_size) {
    const float* x      = (const float*)d_in[0];
    const int*   W      = (const int*)  d_in[1];
    const int*   zeros  = (const int*)  d_in[2];
    const float* scales = (const float*)d_in[3];
    const float* loraA  = (const float*)d_in[4];
    const float* loraB  = (const float*)d_in[5];
    float* out = (float*)d_out;

    cudaFuncSetAttribute(qmain_kernel,
                         cudaFuncAttributeMaxDynamicSharedMemorySize, SMEM_BYTES);

    dim3 pgrid(MTOT, 4);
    prep_kernel<<<pgrid, 256>>>(x, loraA);

    const int nblocks = NFMA + (OUTD / NTILE) * KSPLIT_T;   // 86 + 688
    qmain_kernel<<<nblocks, 256, SMEM_BYTES>>>(x, W, zeros, scales, loraB);

    dim3 rgrid((OUTD / 4 + 255) / 256, MTOT);
    reduce_kernel<<<rgrid, 256>>>(out);
}

// round 11
// speedup vs baseline: 1.2157x; 1.2157x over previous
#include <cuda_runtime.h>
#include <cuda_fp16.h>
#include <stdint.h>

// QLoRALinear: out[128,11008] = x @ dequant_int4(W) + 2*(x@A^T)@B^T
// Round 11: fp16 single-term mma (factored scales, (q-z) exact), KSPLIT=8,
// reduction + LoRA fused into main via threadfence last-block pattern.

#define OUTD 11008
#define IND  4096
#define MTOT 128
#define RLORA 16

#define NTILE 64                    // o per block
#define KSPLIT 8
#define KC 64                       // k per chunk
#define NCH (IND / KSPLIT / KC)     // 8 chunks per block
#define NGRP (NCH / 2)              // 4 groups per block
#define NCHUNK_TOT (IND / KC)       // 64 tiles in prep layout
#define ROWH 72                     // halves per tile row (64 data + 8 pad)
#define NOTILE (OUTD / NTILE)       // 172

// per-buffer smem offsets (halves)
#define XH_OFF 0
#define WQ_OFF 9216                 // 128*72
#define BUF_H  13824                // + 64*72
#define SMEM_BYTES (2 * BUF_H * 2)  // 55296 B dynamic

// ---- device scratch ----
__device__ __align__(16) uint16_t g_xh[NCHUNK_TOT * MTOT * ROWH];  // fp16 x tiles
__device__ __align__(16) float    g_xa4[4 * MTOT * RLORA];         // xa partial slabs
__device__ float g_partial[KSPLIT * MTOT * OUTD];                  // 45 MB
__device__ int   g_cnt[NOTILE];                                    // zero-init

// ---------------------------------------------------------------------------
__device__ __forceinline__ uint32_t pack_f16x2(float lo, float hi) {
    uint32_t r;
    asm("cvt.rn.f16x2.f32 %0, %1, %2;" : "=r"(r) : "f"(hi), "f"(lo));
    return r;
}
__device__ __forceinline__ uint32_t smem_u32(const void* p) {
    uint32_t a;
    asm("{ .reg .u64 t; cvta.to.shared.u64 t, %1; cvt.u32.u64 %0, t; }"
        : "=r"(a) : "l"(p));
    return a;
}
__device__ __forceinline__ void cp16(uint32_t dst, const void* src) {
    asm volatile("cp.async.cg.shared.global [%0], [%1], 16;"
                 :: "r"(dst), "l"(src) : "memory");
}
__device__ __forceinline__ void mma16816(float* d, const uint32_t* a,
                                         uint32_t b0, uint32_t b1) {
    asm volatile(
        "mma.sync.aligned.m16n8k16.row.col.f32.f16.f16.f32 "
        "{%0,%1,%2,%3}, {%4,%5,%6,%7}, {%8,%9}, {%0,%1,%2,%3};"
        : "+f"(d[0]), "+f"(d[1]), "+f"(d[2]), "+f"(d[3])
        : "r"(a[0]), "r"(a[1]), "r"(a[2]), "r"(a[3]), "r"(b0), "r"(b1));
}
__device__ __forceinline__ void ldm4(uint32_t* r, uint32_t addr) {
    asm volatile("ldmatrix.sync.aligned.m8n8.x4.shared.b16 {%0,%1,%2,%3}, [%4];"
                 : "=r"(r[0]), "=r"(r[1]), "=r"(r[2]), "=r"(r[3]) : "r"(addr));
}

// ---------------------------------------------------------------------------
// Prep: x -> fp16 tile image + xa slab (no atomics). grid (128, 4), 256 thr.
// ---------------------------------------------------------------------------
__global__ __launch_bounds__(256) void prep_kernel(const float* __restrict__ x,
                                                   const float* __restrict__ A) {
    const int m  = blockIdx.x;
    const int kq = blockIdx.y;
    const int t  = threadIdx.x;
    const int wid = t >> 5, lane = t & 31;
    const int k0 = kq * 1024 + t * 4;

    const float4 xv = *(const float4*)(x + (size_t)m * IND + k0);

    const int chunk = k0 >> 6;
    const int koff  = k0 & 63;
    uint2 hp;
    hp.x = pack_f16x2(xv.x, xv.y);
    hp.y = pack_f16x2(xv.z, xv.w);
    *(uint2*)(g_xh + ((size_t)chunk * MTOT + m) * ROWH + koff) = hp;

    float acc[RLORA];
#pragma unroll
    for (int r = 0; r < RLORA; r++) {
        const float4 a4 = *(const float4*)(A + (size_t)r * IND + k0);
        float s = xv.x * a4.x;
        s = fmaf(xv.y, a4.y, s);
        s = fmaf(xv.z, a4.z, s);
        s = fmaf(xv.w, a4.w, s);
        acc[r] = s;
    }
#pragma unroll
    for (int r = 0; r < RLORA; r++)
#pragma unroll
        for (int off = 16; off > 0; off >>= 1)
            acc[r] += __shfl_xor_sync(0xffffffffu, acc[r], off);

    __shared__ float red[8][RLORA];
    if (lane == 0)
#pragma unroll
        for (int r = 0; r < RLORA; r++) red[wid][r] = acc[r];
    __syncthreads();
    if (t < RLORA) {
        float s = 0.0f;
#pragma unroll
        for (int w = 0; w < 8; w++) s += red[w][t];
        g_xa4[(kq * MTOT + m) * RLORA + t] = s;
    }
}

// ---------------------------------------------------------------------------
// Main GEMM: grid 1376 (172 o-tiles x 8 k-slabs), 256 threads.
// Last-arriving slab block per o-tile performs the reduction + LoRA + store.
// ---------------------------------------------------------------------------
__global__ __launch_bounds__(256, 2) void qmain_kernel(
    const int*   __restrict__ W,
    const int*   __restrict__ zeros,
    const float* __restrict__ scales,
    const float* __restrict__ loraB,
    float*       __restrict__ out)
{
    extern __shared__ __align__(16) uint16_t smdyn[];
    __shared__ float sS[NGRP][NTILE];
    __shared__ int   zS[NGRP][NTILE];
    __shared__ __align__(16) float sB[NTILE][RLORA];
    __shared__ __align__(16) float sxa[MTOT][RLORA];
    __shared__ int isLast;
    const uint32_t smb = smem_u32(smdyn);

    const int t = threadIdx.x;
    const int lane = t & 31;
    const int wid = t >> 5;
    const int wm = wid & 3;
    const int wo = wid >> 2;
    const int otile = blockIdx.x >> 3;
    const int kq = blockIdx.x & 7;
    const int obase = otile * NTILE;
    const int gbase = kq * NGRP;

    const int so  = t & 63;
    const int skq = t >> 6;
    const int xrow = t >> 1;
    const int xhalf = t & 1;

    // stage scales / zeros (256 entries)
    {
        const int g = t >> 6, o = t & 63;
        sS[g][o] = scales[(size_t)(gbase + g) * OUTD + obase + o];
        zS[g][o] = zeros[(size_t)(gbase + g) * OUTD + obase + o];
    }

    const int rowA = (lane & 7) + ((lane >> 3) & 1) * 8;
    const int kA   = ((lane >> 4) & 1) * 8;
    const int rowB = (lane & 7) + ((lane >> 4) & 1) * 8;
    const int kB   = ((lane >> 3) & 1) * 8;

    float facc[2][4][4];
    float gacc[2][4][4];
#pragma unroll
    for (int mt = 0; mt < 2; mt++)
#pragma unroll
        for (int ot = 0; ot < 4; ot++)
#pragma unroll
            for (int i = 0; i < 4; i++) { facc[mt][ot][i] = 0.f; gacc[mt][ot][i] = 0.f; }

    auto cpX = [&](int b, int c) {
        const int ck = kq * NCH + c;
        const size_t src = ((size_t)ck * MTOT + xrow) * ROWH + xhalf * 32;
        const uint32_t dxh = smb + (b * BUF_H + XH_OFF + xrow * ROWH + xhalf * 32) * 2;
#pragma unroll
        for (int j = 0; j < 4; j++)
            cp16(dxh + j * 16, g_xh + src + j * 8);
        asm volatile("cp.async.commit_group;" ::: "memory");
    };
    auto ldgW = [&](int c, int* qv) {
        const int ck = kq * NCH + c;
        const int* Wp = W + (size_t)(ck * KC + skq * 16) * OUTD + obase + so;
#pragma unroll
        for (int p = 0; p < 16; p++) qv[p] = Wp[(size_t)p * OUTD];
    };
    auto stsW = [&](int b, int c, const int* qv) {
        const int z = zS[c >> 1][so];
        uint32_t hp[8];
#pragma unroll
        for (int p = 0; p < 8; p++)
            hp[p] = pack_f16x2((float)(qv[2 * p] - z), (float)(qv[2 * p + 1] - z));
        uint16_t* wq = smdyn + b * BUF_H + WQ_OFF + so * ROWH + skq * 16;
        ((uint4*)wq)[0] = make_uint4(hp[0], hp[1], hp[2], hp[3]);
        ((uint4*)wq)[1] = make_uint4(hp[4], hp[5], hp[6], hp[7]);
    };

    __syncthreads();   // sS/zS ready

    // prologue
    int qv[16];
    ldgW(0, qv);
    cpX(0, 0);
    stsW(0, 0, qv);
    asm volatile("cp.async.wait_group 0;" ::: "memory");
    __syncthreads();

    const int arow = lane >> 2;
    const int acol = (lane & 3) * 2;

    const int aoff0 = XH_OFF + (wm * 32 + 0 * 16 + rowA) * ROWH + kA;
    const int aoff1 = XH_OFF + (wm * 32 + 1 * 16 + rowA) * ROWH + kA;
    const int boff0 = WQ_OFF + (wo * 32 + 0 * 16 + rowB) * ROWH + kB;
    const int boff1 = WQ_OFF + (wo * 32 + 1 * 16 + rowB) * ROWH + kB;

    int buf = 0;
#pragma unroll 1
    for (int c = 0; c < NCH; c++) {
        int qn[16];
        if (c + 1 < NCH) {
            ldgW(c + 1, qn);
            cpX(buf ^ 1, c + 1);
        }

        const uint32_t bb = smb + (buf * BUF_H) * 2;
#pragma unroll
        for (int ks = 0; ks < KC; ks += 16) {
            uint32_t a0[4], a1[4], bq0[4], bq1[4];
            ldm4(a0, bb + (aoff0 + ks) * 2);
            ldm4(a1, bb + (aoff1 + ks) * 2);
            ldm4(bq0, bb + (boff0 + ks) * 2);
            ldm4(bq1, bb + (boff1 + ks) * 2);
#pragma unroll
            for (int ot = 0; ot < 4; ot++) {
                const uint32_t b0 = (ot < 2) ? bq0[2 * ot]     : bq1[2 * (ot - 2)];
                const uint32_t b1 = (ot < 2) ? bq0[2 * ot + 1] : bq1[2 * (ot - 2) + 1];
                mma16816(gacc[0][ot], a0, b0, b1);
                mma16816(gacc[1][ot], a1, b0, b1);
            }
        }

        if (c + 1 < NCH) stsW(buf ^ 1, c + 1, qn);

        if (c & 1) {
            const int g = c >> 1;
#pragma unroll
            for (int ot = 0; ot < 4; ot++) {
                const float2 sv = *(const float2*)&sS[g][wo * 32 + ot * 8 + acol];
#pragma unroll
                for (int mt = 0; mt < 2; mt++) {
                    facc[mt][ot][0] = fmaf(sv.x, gacc[mt][ot][0], facc[mt][ot][0]);
                    facc[mt][ot][1] = fmaf(sv.y, gacc[mt][ot][1], facc[mt][ot][1]);
                    facc[mt][ot][2] = fmaf(sv.x, gacc[mt][ot][2], facc[mt][ot][2]);
                    facc[mt][ot][3] = fmaf(sv.y, gacc[mt][ot][3], facc[mt][ot][3]);
                    gacc[mt][ot][0] = 0.f; gacc[mt][ot][1] = 0.f;
                    gacc[mt][ot][2] = 0.f; gacc[mt][ot][3] = 0.f;
                }
            }
        }

        asm volatile("cp.async.wait_group 0;" ::: "memory");
        __syncthreads();
        buf ^= 1;
    }

    // ---- store this slab's partial tile ----
    float* pp = g_partial + (size_t)kq * MTOT * OUTD;
#pragma unroll
    for (int mt = 0; mt < 2; mt++) {
        const int r0 = wm * 32 + mt * 16 + arow;
#pragma unroll
        for (int ot = 0; ot < 4; ot++) {
            const int cabs = obase + wo * 32 + ot * 8 + acol;
            *(float2*)&pp[(size_t)r0 * OUTD + cabs] =
                make_float2(facc[mt][ot][0], facc[mt][ot][1]);
            *(float2*)&pp[(size_t)(r0 + 8) * OUTD + cabs] =
                make_float2(facc[mt][ot][2], facc[mt][ot][3]);
        }
    }

    // ---- last-block reduction + LoRA + output ----
    __threadfence();
    __syncthreads();
    if (t == 0) {
        const int old = atomicAdd(&g_cnt[otile], 1);
        isLast = (old == KSPLIT - 1);
        if (isLast) g_cnt[otile] = 0;   // reset for next launch (graph replay)
    }
    __syncthreads();
    if (!isLast) return;

    // stage loraB tile + xa (sum 4 prep slabs, scale by 2)
    ((float4*)sB)[t] = ((const float4*)(loraB + (size_t)obase * RLORA))[t];
#pragma unroll
    for (int pass = 0; pass < 2; pass++) {
        const int idx = t + pass * 256;
        float4 s0 = ((const float4*)g_xa4)[idx];
        const float4 s1 = ((const float4*)g_xa4)[idx + 512];
        const float4 s2 = ((const float4*)g_xa4)[idx + 1024];
        const float4 s3 = ((const float4*)g_xa4)[idx + 1536];
        s0.x = 2.0f * (s0.x + s1.x + s2.x + s3.x);
        s0.y = 2.0f * (s0.y + s1.y + s2.y + s3.y);
        s0.z = 2.0f * (s0.z + s1.z + s2.z + s3.z);
        s0.w = 2.0f * (s0.w + s1.w + s2.w + s3.w);
        ((float4*)sxa)[idx] = s0;
    }
    __syncthreads();

    // 2048 float4 outputs in the 128 x 64 tile; 8 per thread, coalesced
#pragma unroll
    for (int j = 0; j < 8; j++) {
        const int idx = t + j * 256;       // 0..2047
        const int m   = idx >> 4;          // 16 float4 per m-row
        const int oq  = idx & 15;
        const size_t goff = (size_t)m * OUTD + obase + oq * 4;

        float4 s = make_float4(0.f, 0.f, 0.f, 0.f);
#pragma unroll
        for (int p = 0; p < KSPLIT; p++) {
            const float4 v = *(const float4*)&g_partial[(size_t)p * MTOT * OUTD + goff];
            s.x += v.x; s.y += v.y; s.z += v.z; s.w += v.w;
        }

        const float* xr = sxa[m];
        const int o0 = oq * 4;
        float l[4] = {0.f, 0.f, 0.f, 0.f};
#pragma unroll
        for (int e = 0; e < 4; e++) {
            const float* Bp = sB[o0 + e];
#pragma unroll
            for (int rr = 0; rr < RLORA; rr += 4) {
                const float4 b4 = *(const float4*)(Bp + rr);
                l[e] = fmaf(xr[rr + 0], b4.x, l[e]);
                l[e] = fmaf(xr[rr + 1], b4.y, l[e]);
                l[e] = fmaf(xr[rr + 2], b4.z, l[e]);
                l[e] = fmaf(xr[rr + 3], b4.w, l[e]);
            }
        }
        s.x += l[0]; s.y += l[1]; s.z += l[2]; s.w += l[3];
        *(float4*)&out[goff] = s;
    }
}

// ---------------------------------------------------------------------------
extern "C" void kernel_launch(void* const* d_in, const int* in_sizes, int n_in,
                              void* d_out, int out_size) {
    const float* x      = (const float*)d_in[0];
    const int*   W      = (const int*)  d_in[1];
    const int*   zeros  = (const int*)  d_in[2];
    const float* scales = (const float*)d_in[3];
    const float* loraA  = (const float*)d_in[4];
    const float* loraB  = (const float*)d_in[5];
    float* out = (float*)d_out;

    cudaFuncSetAttribute(qmain_kernel,
                         cudaFuncAttributeMaxDynamicSharedMemorySize, SMEM_BYTES);

    dim3 pgrid(MTOT, 4);
    prep_kernel<<<pgrid, 256>>>(x, loraA);

    qmain_kernel<<<NOTILE * KSPLIT, 256, SMEM_BYTES>>>(W, zeros, scales, loraB, out);
}

// round 12
// speedup vs baseline: 1.3979x; 1.1499x over previous
#include <cuda_runtime.h>
#include <cuda_fp16.h>
#include <stdint.h>

// QLoRALinear: out[128,11008] = x @ dequant_int4(W) + 2*(x@A^T)@B^T
// Round 12: fp16 mma, W fully dequantized to fp16 at stage time (no per-group
// fold -> -32 regs), __launch_bounds__(256,3) for 3 blocks/SM, KSPLIT=8,
// separate reduce kernel with smem-staged LoRA.

#define OUTD 11008
#define IND  4096
#define MTOT 128
#define RLORA 16

#define NTILE 64                    // o per block
#define KSPLIT 8
#define KC 64                       // k per chunk
#define NCH (IND / KSPLIT / KC)     // 8 chunks per block
#define NGRP (NCH / 2)              // 4 quant groups per slab
#define NCHUNK_TOT (IND / KC)       // 64 tiles in prep layout
#define ROWH 72                     // halves per tile row (64 data + 8 pad)
#define NOTILE (OUTD / NTILE)       // 172

// per-buffer smem offsets (halves)
#define XH_OFF 0
#define WQ_OFF 9216                 // 128*72
#define BUF_H  13824                // + 64*72
#define SMEM_BYTES (2 * BUF_H * 2)  // 55296 B dynamic

// ---- device scratch ----
__device__ __align__(16) uint16_t g_xh[NCHUNK_TOT * MTOT * ROWH];  // fp16 x tiles
__device__ __align__(16) float    g_xa4[4 * MTOT * RLORA];         // xa partial slabs
__device__ float g_partial[KSPLIT * MTOT * OUTD];                  // 45 MB

// ---------------------------------------------------------------------------
__device__ __forceinline__ uint32_t pack_f16x2(float lo, float hi) {
    uint32_t r;
    asm("cvt.rn.f16x2.f32 %0, %1, %2;" : "=r"(r) : "f"(hi), "f"(lo));
    return r;
}
__device__ __forceinline__ uint32_t smem_u32(const void* p) {
    uint32_t a;
    asm("{ .reg .u64 t; cvta.to.shared.u64 t, %1; cvt.u32.u64 %0, t; }"
        : "=r"(a) : "l"(p));
    return a;
}
__device__ __forceinline__ void cp16(uint32_t dst, const void* src) {
    asm volatile("cp.async.cg.shared.global [%0], [%1], 16;"
                 :: "r"(dst), "l"(src) : "memory");
}
__device__ __forceinline__ void mma16816(float* d, const uint32_t* a,
                                         uint32_t b0, uint32_t b1) {
    asm volatile(
        "mma.sync.aligned.m16n8k16.row.col.f32.f16.f16.f32 "
        "{%0,%1,%2,%3}, {%4,%5,%6,%7}, {%8,%9}, {%0,%1,%2,%3};"
        : "+f"(d[0]), "+f"(d[1]), "+f"(d[2]), "+f"(d[3])
        : "r"(a[0]), "r"(a[1]), "r"(a[2]), "r"(a[3]), "r"(b0), "r"(b1));
}
__device__ __forceinline__ void ldm4(uint32_t* r, uint32_t addr) {
    asm volatile("ldmatrix.sync.aligned.m8n8.x4.shared.b16 {%0,%1,%2,%3}, [%4];"
                 : "=r"(r[0]), "=r"(r[1]), "=r"(r[2]), "=r"(r[3]) : "r"(addr));
}

// ---------------------------------------------------------------------------
// Prep: x -> fp16 tile image + xa slab. grid (128, 4), 256 thr.
// ---------------------------------------------------------------------------
__global__ __launch_bounds__(256) void prep_kernel(const float* __restrict__ x,
                                                   const float* __restrict__ A) {
    const int m  = blockIdx.x;
    const int kq = blockIdx.y;
    const int t  = threadIdx.x;
    const int wid = t >> 5, lane = t & 31;
    const int k0 = kq * 1024 + t * 4;

    const float4 xv = *(const float4*)(x + (size_t)m * IND + k0);

    const int chunk = k0 >> 6;
    const int koff  = k0 & 63;
    uint2 hp;
    hp.x = pack_f16x2(xv.x, xv.y);
    hp.y = pack_f16x2(xv.z, xv.w);
    *(uint2*)(g_xh + ((size_t)chunk * MTOT + m) * ROWH + koff) = hp;

    float acc[RLORA];
#pragma unroll
    for (int r = 0; r < RLORA; r++) {
        const float4 a4 = *(const float4*)(A + (size_t)r * IND + k0);
        float s = xv.x * a4.x;
        s = fmaf(xv.y, a4.y, s);
        s = fmaf(xv.z, a4.z, s);
        s = fmaf(xv.w, a4.w, s);
        acc[r] = s;
    }
#pragma unroll
    for (int r = 0; r < RLORA; r++)
#pragma unroll
        for (int off = 16; off > 0; off >>= 1)
            acc[r] += __shfl_xor_sync(0xffffffffu, acc[r], off);

    __shared__ float red[8][RLORA];
    if (lane == 0)
#pragma unroll
        for (int r = 0; r < RLORA; r++) red[wid][r] = acc[r];
    __syncthreads();
    if (t < RLORA) {
        float s = 0.0f;
#pragma unroll
        for (int w = 0; w < 8; w++) s += red[w][t];
        g_xa4[(kq * MTOT + m) * RLORA + t] = s;
    }
}

// ---------------------------------------------------------------------------
// Main GEMM: grid 1376 (172 o-tiles x 8 k-slabs), 256 threads, 3 blocks/SM.
// ---------------------------------------------------------------------------
__global__ __launch_bounds__(256, 3) void qmain_kernel(
    const int*   __restrict__ W,
    const int*   __restrict__ zeros,
    const float* __restrict__ scales)
{
    extern __shared__ __align__(16) uint16_t smdyn[];
    __shared__ float2 szs[NGRP][NTILE];   // (s, z*s) per group/o : 2 KB
    const uint32_t smb = smem_u32(smdyn);

    const int t = threadIdx.x;
    const int lane = t & 31;
    const int wid = t >> 5;
    const int wm = wid & 3;
    const int wo = wid >> 2;
    const int otile = blockIdx.x >> 3;
    const int kq = blockIdx.x & 7;
    const int obase = otile * NTILE;
    const int gbase = kq * NGRP;

    const int so  = t & 63;
    const int skq = t >> 6;
    const int xrow = t >> 1;
    const int xhalf = t & 1;

    // stage (s, z*s) — 256 entries
    {
        const int g = t >> 6, o = t & 63;
        const float s = scales[(size_t)(gbase + g) * OUTD + obase + o];
        const float z = (float)zeros[(size_t)(gbase + g) * OUTD + obase + o];
        szs[g][o] = make_float2(s, z * s);
    }

    const int rowA = (lane & 7) + ((lane >> 3) & 1) * 8;
    const int kA   = ((lane >> 4) & 1) * 8;
    const int rowB = (lane & 7) + ((lane >> 4) & 1) * 8;
    const int kB   = ((lane >> 3) & 1) * 8;

    float facc[2][4][4];
#pragma unroll
    for (int mt = 0; mt < 2; mt++)
#pragma unroll
        for (int ot = 0; ot < 4; ot++)
#pragma unroll
            for (int i = 0; i < 4; i++) facc[mt][ot][i] = 0.f;

    auto cpX = [&](int b, int c) {
        const int ck = kq * NCH + c;
        const size_t src = ((size_t)ck * MTOT + xrow) * ROWH + xhalf * 32;
        const uint32_t dxh = smb + (b * BUF_H + XH_OFF + xrow * ROWH + xhalf * 32) * 2;
#pragma unroll
        for (int j = 0; j < 4; j++)
            cp16(dxh + j * 16, g_xh + src + j * 8);
        asm volatile("cp.async.commit_group;" ::: "memory");
    };
    auto ldgW = [&](int c, int* qv) {
        const int ck = kq * NCH + c;
        const int* Wp = W + (size_t)(ck * KC + skq * 16) * OUTD + obase + so;
#pragma unroll
        for (int p = 0; p < 16; p++) qv[p] = Wp[(size_t)p * OUTD];
    };
    auto stsW = [&](int b, int c, const int* qv) {
        const float2 sz = szs[c >> 1][so];
        uint32_t hp[8];
#pragma unroll
        for (int p = 0; p < 8; p++) {
            const float f0 = fmaf((float)qv[2 * p],     sz.x, -sz.y);
            const float f1 = fmaf((float)qv[2 * p + 1], sz.x, -sz.y);
            hp[p] = pack_f16x2(f0, f1);
        }
        uint16_t* wq = smdyn + b * BUF_H + WQ_OFF + so * ROWH + skq * 16;
        ((uint4*)wq)[0] = make_uint4(hp[0], hp[1], hp[2], hp[3]);
        ((uint4*)wq)[1] = make_uint4(hp[4], hp[5], hp[6], hp[7]);
    };

    __syncthreads();   // szs ready

    // prologue
    int qv[16];
    ldgW(0, qv);
    cpX(0, 0);
    stsW(0, 0, qv);
    asm volatile("cp.async.wait_group 0;" ::: "memory");
    __syncthreads();

    const int arow = lane >> 2;
    const int acol = (lane & 3) * 2;

    const int aoff0 = XH_OFF + (wm * 32 + 0 * 16 + rowA) * ROWH + kA;
    const int aoff1 = XH_OFF + (wm * 32 + 1 * 16 + rowA) * ROWH + kA;
    const int boff0 = WQ_OFF + (wo * 32 + 0 * 16 + rowB) * ROWH + kB;
    const int boff1 = WQ_OFF + (wo * 32 + 1 * 16 + rowB) * ROWH + kB;

    int buf = 0;
#pragma unroll 1
    for (int c = 0; c < NCH; c++) {
        int qn[16];
        if (c + 1 < NCH) {
            ldgW(c + 1, qn);
            cpX(buf ^ 1, c + 1);
        }

        const uint32_t bb = smb + (buf * BUF_H) * 2;
#pragma unroll
        for (int ks = 0; ks < KC; ks += 16) {
            uint32_t a0[4], a1[4], bq0[4], bq1[4];
            ldm4(a0, bb + (aoff0 + ks) * 2);
            ldm4(a1, bb + (aoff1 + ks) * 2);
            ldm4(bq0, bb + (boff0 + ks) * 2);
            ldm4(bq1, bb + (boff1 + ks) * 2);
#pragma unroll
            for (int ot = 0; ot < 4; ot++) {
                const uint32_t b0 = (ot < 2) ? bq0[2 * ot]     : bq1[2 * (ot - 2)];
                const uint32_t b1 = (ot < 2) ? bq0[2 * ot + 1] : bq1[2 * (ot - 2) + 1];
                mma16816(facc[0][ot], a0, b0, b1);
                mma16816(facc[1][ot], a1, b0, b1);
            }
        }

        if (c + 1 < NCH) stsW(buf ^ 1, c + 1, qn);

        asm volatile("cp.async.wait_group 0;" ::: "memory");
        __syncthreads();
        buf ^= 1;
    }

    // ---- store this slab's partial tile ----
    float* pp = g_partial + (size_t)kq * MTOT * OUTD;
#pragma unroll
    for (int mt = 0; mt < 2; mt++) {
        const int r0 = wm * 32 + mt * 16 + arow;
#pragma unroll
        for (int ot = 0; ot < 4; ot++) {
            const int cabs = obase + wo * 32 + ot * 8 + acol;
            *(float2*)&pp[(size_t)r0 * OUTD + cabs] =
                make_float2(facc[mt][ot][0], facc[mt][ot][1]);
            *(float2*)&pp[(size_t)(r0 + 8) * OUTD + cabs] =
                make_float2(facc[mt][ot][2], facc[mt][ot][3]);
        }
    }
}

// ---------------------------------------------------------------------------
// Reduce: 8-way partial sum + LoRA (smem-staged). grid (172, 2), 256 thr.
// Block covers 64 o x 64 m.
// ---------------------------------------------------------------------------
__global__ __launch_bounds__(256) void reduce_kernel(
    const float* __restrict__ loraB,
    float*       __restrict__ out)
{
    __shared__ __align__(16) float sB[NTILE][RLORA];    // 4 KB
    __shared__ __align__(16) float sxa[64][RLORA];      // 4 KB

    const int t = threadIdx.x;
    const int obase = blockIdx.x * NTILE;
    const int mbase = blockIdx.y * 64;

    // stage loraB tile (64 o x 16 r, contiguous) : 256 float4
    ((float4*)sB)[t] = ((const float4*)(loraB + (size_t)obase * RLORA))[t];
    // stage xa for this m-range: sum 4 prep slabs, scale by 2 : 256 float4
    {
        const int mloc = t >> 2, r4 = t & 3;
        const int fidx = (mbase + mloc) * 4 + r4;       // float4 idx into [128][16]
        float4 s0 = ((const float4*)g_xa4)[fidx];
        const float4 s1 = ((const float4*)g_xa4)[fidx + 512];
        const float4 s2 = ((const float4*)g_xa4)[fidx + 1024];
        const float4 s3 = ((const float4*)g_xa4)[fidx + 1536];
        s0.x = 2.0f * (s0.x + s1.x + s2.x + s3.x);
        s0.y = 2.0f * (s0.y + s1.y + s2.y + s3.y);
        s0.z = 2.0f * (s0.z + s1.z + s2.z + s3.z);
        s0.w = 2.0f * (s0.w + s1.w + s2.w + s3.w);
        ((float4*)sxa)[t] = s0;
    }
    __syncthreads();

    // 64m x 16 float4 = 1024 float4; 4 per thread
#pragma unroll
    for (int j = 0; j < 4; j++) {
        const int idx = t + j * 256;
        const int mloc = idx >> 4;
        const int oq = idx & 15;
        const size_t goff = (size_t)(mbase + mloc) * OUTD + obase + oq * 4;

        float4 s = make_float4(0.f, 0.f, 0.f, 0.f);
#pragma unroll
        for (int p = 0; p < KSPLIT; p++) {
            const float4 v = *(const float4*)&g_partial[(size_t)p * MTOT * OUTD + goff];
            s.x += v.x; s.y += v.y; s.z += v.z; s.w += v.w;
        }

        const float* xr = sxa[mloc];
        const int o0 = oq * 4;
        float l[4] = {0.f, 0.f, 0.f, 0.f};
#pragma unroll
        for (int e = 0; e < 4; e++) {
            const float* Bp = sB[o0 + e];
#pragma unroll
            for (int rr = 0; rr < RLORA; rr += 4) {
                const float4 b4 = *(const float4*)(Bp + rr);
                l[e] = fmaf(xr[rr + 0], b4.x, l[e]);
                l[e] = fmaf(xr[rr + 1], b4.y, l[e]);
                l[e] = fmaf(xr[rr + 2], b4.z, l[e]);
                l[e] = fmaf(xr[rr + 3], b4.w, l[e]);
            }
        }
        s.x += l[0]; s.y += l[1]; s.z += l[2]; s.w += l[3];
        *(float4*)&out[goff] = s;
    }
}

// ---------------------------------------------------------------------------
extern "C" void kernel_launch(void* const* d_in, const int* in_sizes, int n_in,
                              void* d_out, int out_size) {
    const float* x      = (const float*)d_in[0];
    const int*   W      = (const int*)  d_in[1];
    const int*   zeros  = (const int*)  d_in[2];
    const float* scales = (const float*)d_in[3];
    const float* loraA  = (const float*)d_in[4];
    const float* loraB  = (const float*)d_in[5];
    float* out = (float*)d_out;

    cudaFuncSetAttribute(qmain_kernel,
                         cudaFuncAttributeMaxDynamicSharedMemorySize, SMEM_BYTES);

    dim3 pgrid(MTOT, 4);
    prep_kernel<<<pgrid, 256>>>(x, loraA);

    qmain_kernel<<<NOTILE * KSPLIT, 256, SMEM_BYTES>>>(W, zeros, scales);

    dim3 rgrid(NOTILE, 2);
    reduce_kernel<<<rgrid, 256>>>(loraB, out);
}